// round 15
// baseline (speedup 1.0000x reference)
#include <cuda_runtime.h>
#include <math.h>

// ---------------------------------------------------------------------------
// NUFFT adjoint (Kaiser-Bessel gridding) for GB300 — round 15
// = R14 (fused radix-16 FFT stages, R9 scatter/zero, g_fx intermediate)
// + fft_x column-pairing restored IN-BLOCK (R9 style): block = (iy, -iy),
//   512 threads / 8 FFTs -> every grid cell read once from L2 (64 MB not
//   128 MB); intra-block reuse hits L1. No race: output still goes to g_fx.
// + fft_y also 512 threads / 8 FFTs (2 output rows/block), shared FFT code.
// + PITCH=1090 (row stride = 4 banks) keeps all FFT accesses conflict-free
//   with 8 rows.
// ---------------------------------------------------------------------------

#define KGRID   1024
#define NIMG    512
#define MPTS    200000
#define BATCH   8
#define JW      6
#define BETA_F  14.04f
#define PI_F    3.14159265358979f

#define GRID_F2 (KGRID * KGRID * BATCH)   // 64 MB
#define FX_F2   (NIMG * KGRID * 4)        // 16 MB packed fft_x output
#define PITCH   1090                      // 17*64 data + 2 pad (PITCH%16==2)

#define TW_OFF1 0
#define TW_OFF2 12
#define TW_OFF3 60
#define TW_OFF4 252
#define TW_TOT  1020

__device__ float2 g_grid[GRID_F2];
__device__ float2 g_fx[FX_F2];            // [xl][ky][p], xl = compacted row

// padded position of logical element n within a row
__device__ __forceinline__ int pos17(int n) { return 17 * (n >> 4) + (n & 15); }

// ---------------------------------------------------------------------------
__device__ __forceinline__ float bessel_i0(float x)
{
    if (x < 3.75f) {
        float t = x * (1.0f / 3.75f);
        t *= t;
        return 1.0f + t * (3.5156229f + t * (3.0899424f + t * (1.2067492f +
                     t * (0.2659732f + t * (0.0360768f + t * 0.0045813f)))));
    } else {
        float t = 3.75f / x;
        float p = 0.39894228f + t * (0.01328592f + t * (0.00225319f +
                  t * (-0.00157565f + t * (0.00916281f + t * (-0.02057706f +
                  t * (0.02635537f + t * (-0.01647633f + t * 0.00392377f)))))));
        return __expf(x) * rsqrtf(x) * p;
    }
}

// ---------------------------------------------------------------------------
// Zero the grid (64 MB). Also the L2 warm for the scatter's atomics.
// ---------------------------------------------------------------------------
__global__ void zero_kernel()
{
    float4* p = reinterpret_cast<float4*>(g_grid);
    const int n = GRID_F2 / 2;
    for (int i = blockIdx.x * blockDim.x + threadIdx.x; i < n;
         i += gridDim.x * blockDim.x)
        p[i] = make_float4(0.f, 0.f, 0.f, 0.f);
}

// ---------------------------------------------------------------------------
// Gridding scatter (R9): 8 threads per measurement; q = batch pair (lanes
// 0-3 write 4 contiguous 16B quarters of each 64B cell), h = x-tap half.
// ---------------------------------------------------------------------------
__global__ __launch_bounds__(256)
void scatter_kernel(const float* __restrict__ yr, const float* __restrict__ yi,
                    const float* __restrict__ uv, const float* __restrict__ wts)
{
    const int gid = blockIdx.x * blockDim.x + threadIdx.x;
    const int m = gid >> 3;
    const int q = gid & 3;                 // batches 2q, 2q+1
    const int h = (gid >> 2) & 1;          // a in {3h, 3h+1, 3h+2}
    if (m >= MPTS) return;

    const float2 c2 = reinterpret_cast<const float2*>(uv)[m];
    const float wt = wts[m];
    const float inv_i0b = 1.0f / bessel_i0(BETA_F);

    int ixv[3], iyv[JW];
    float wx[3], wy[JW];

    {
        float k  = c2.x / (2.0f * PI_F) * (float)KGRID;
        float km = floorf(k - 3.0f);
        #pragma unroll
        for (int j = 0; j < 3; j++) {
            int jj = 3 * h + j;
            float pt = km + (float)(jj + 1);
            float d  = k - pt;
            float arg = fmaxf(1.0f - d * d * (1.0f / 9.0f), 0.0f);
            wx[j] = bessel_i0(BETA_F * sqrtf(arg)) * inv_i0b;
            ixv[j] = ((int)pt + KGRID) & (KGRID - 1);
        }
    }
    {
        float k  = c2.y / (2.0f * PI_F) * (float)KGRID;
        float km = floorf(k - 3.0f);
        #pragma unroll
        for (int j = 0; j < JW; j++) {
            float pt = km + (float)(j + 1);
            float d  = k - pt;
            float arg = fmaxf(1.0f - d * d * (1.0f / 9.0f), 0.0f);
            wy[j] = bessel_i0(BETA_F * sqrtf(arg)) * inv_i0b;
            iyv[j] = ((int)pt + KGRID) & (KGRID - 1);
        }
    }

    const int b0 = 2 * q;
    const float yr0 = yr[b0 * MPTS + m] * wt;
    const float yi0 = yi[b0 * MPTS + m] * wt;
    const float yr1 = yr[(b0 + 1) * MPTS + m] * wt;
    const float yi1 = yi[(b0 + 1) * MPTS + m] * wt;

    #pragma unroll
    for (int a = 0; a < 3; a++) {
        const int rowbase = ixv[a] * KGRID;
        const float wxa = wx[a];
        #pragma unroll
        for (int c = 0; c < JW; c++) {
            const float w2 = wxa * wy[c];
            float* fp = reinterpret_cast<float*>(&g_grid[(rowbase + iyv[c]) * BATCH])
                        + 4 * q;
            asm volatile(
                "red.global.add.v4.f32 [%0], {%1, %2, %3, %4};"
                :: "l"(fp),
                   "f"(w2 * yr0), "f"(w2 * yi0),
                   "f"(w2 * yr1), "f"(w2 * yi1)
                : "memory");
        }
    }
}

// ---------------------------------------------------------------------------
// Radix-4/16 FFT machinery (inverse, e^{+i})
// ---------------------------------------------------------------------------
__device__ __forceinline__ int digit_rev10(int i)
{
    int r = (int)(__brev((unsigned)i) >> 22);
    return ((r & 0x155) << 1) | ((r & 0x2AA) >> 1);
}

__device__ __forceinline__ float2 cmul(float2 a, float2 b)
{
    return make_float2(a.x * b.x - a.y * b.y, a.x * b.y + a.y * b.x);
}

__device__ __forceinline__ void init_tw(float2* tw, int tid, int nthr)
{
    for (int t = tid; t < 340; t += nthr) {
        int s, j, off;
        if      (t < 4)  { s = 1; j = t;      off = TW_OFF1; }
        else if (t < 20) { s = 2; j = t - 4;  off = TW_OFF2; }
        else if (t < 84) { s = 3; j = t - 20; off = TW_OFF3; }
        else             { s = 4; j = t - 84; off = TW_OFF4; }
        int em = j << (8 - 2 * s);
        float a = (float)em * (2.0f * PI_F / 1024.0f);
        float s1, c1, s2, c2, s3, c3;
        __sincosf(a, &s1, &c1);
        __sincosf(2.0f * a, &s2, &c2);
        __sincosf(3.0f * a, &s3, &c3);
        tw[off + 3 * j + 0] = make_float2(c1, s1);
        tw[off + 3 * j + 1] = make_float2(c2, s2);
        tw[off + 3 * j + 2] = make_float2(c3, s3);
    }
}

__device__ __forceinline__ void rad4ip(float2& b0, float2& b1, float2& b2, float2& b3)
{
    float2 t0 = make_float2(b0.x + b2.x, b0.y + b2.y);
    float2 t1 = make_float2(b0.x - b2.x, b0.y - b2.y);
    float2 t2 = make_float2(b1.x + b3.x, b1.y + b3.y);
    float2 t3 = make_float2(-(b1.y - b3.y), b1.x - b3.x);   // +i*(b1-b3)
    b0 = make_float2(t0.x + t2.x, t0.y + t2.y);
    b1 = make_float2(t1.x + t3.x, t1.y + t3.y);
    b2 = make_float2(t0.x - t2.x, t0.y - t2.y);
    b3 = make_float2(t1.x - t3.x, t1.y - t3.y);
}

// stages 0+1: register radix-16 on 16 contiguous elements.
// 512 threads: row = tid&7, group g = tid>>3 (0..63).
__device__ __forceinline__ void stage16_01(float2* data, const float2* tw, int tid)
{
    float2* row = data + (tid & 7) * PITCH;
    const int base = 17 * (tid >> 3);
    float2 v[16];
    #pragma unroll
    for (int k = 0; k < 16; k++) v[k] = row[base + k];

    #pragma unroll
    for (int t = 0; t < 4; t++)                    // stage 0 (twiddle-free)
        rad4ip(v[4 * t], v[4 * t + 1], v[4 * t + 2], v[4 * t + 3]);

    #pragma unroll
    for (int t = 0; t < 4; t++) {                  // stage 1, j = t
        if (t > 0) {
            v[t + 4]  = cmul(v[t + 4],  tw[TW_OFF1 + 3 * t + 0]);
            v[t + 8]  = cmul(v[t + 8],  tw[TW_OFF1 + 3 * t + 1]);
            v[t + 12] = cmul(v[t + 12], tw[TW_OFF1 + 3 * t + 2]);
        }
        rad4ip(v[t], v[t + 4], v[t + 8], v[t + 12]);
    }
    #pragma unroll
    for (int k = 0; k < 16; k++) row[base + k] = v[k];
}

// stages 2+3: register radix-16 on stride-16 elements.
// 512 threads: row = tid&7, j0 = (tid>>3)&15, c = tid>>7 (0..3).
__device__ __forceinline__ void stage16_23(float2* data, const float2* tw, int tid)
{
    float2* row = data + (tid & 7) * PITCH;
    const int j0 = (tid >> 3) & 15;
    const int c  = tid >> 7;
    const int base = 272 * c + j0;
    float2 v[16];
    #pragma unroll
    for (int k = 0; k < 16; k++) v[k] = row[base + 17 * k];

    {   // stage 2: twiddle j = j0
        const float2 w1 = tw[TW_OFF2 + 3 * j0 + 0];
        const float2 w2 = tw[TW_OFF2 + 3 * j0 + 1];
        const float2 w3 = tw[TW_OFF2 + 3 * j0 + 2];
        #pragma unroll
        for (int t = 0; t < 4; t++) {
            v[4 * t + 1] = cmul(v[4 * t + 1], w1);
            v[4 * t + 2] = cmul(v[4 * t + 2], w2);
            v[4 * t + 3] = cmul(v[4 * t + 3], w3);
            rad4ip(v[4 * t], v[4 * t + 1], v[4 * t + 2], v[4 * t + 3]);
        }
    }
    #pragma unroll
    for (int t = 0; t < 4; t++) {                  // stage 3: j = 16t + j0
        const int jj = 16 * t + j0;
        v[t + 4]  = cmul(v[t + 4],  tw[TW_OFF3 + 3 * jj + 0]);
        v[t + 8]  = cmul(v[t + 8],  tw[TW_OFF3 + 3 * jj + 1]);
        v[t + 12] = cmul(v[t + 12], tw[TW_OFF3 + 3 * jj + 2]);
        rad4ip(v[t], v[t + 4], v[t + 8], v[t + 12]);
    }
    #pragma unroll
    for (int k = 0; k < 16; k++) row[base + 17 * k] = v[k];
}

// Final stage (S=4), pruned to fftshift+crop survivors ([0,256) U [768,1024)).
__device__ __forceinline__ void stage4_last_pruned(float2* x, const float2* tw,
                                                   int bi0)
{
    #pragma unroll
    for (int u = 0; u < 4; u++) {
        const int j = bi0 + (u << 6);
        const int b = 17 * (j >> 4) + (j & 15);
        float2 b0 = x[b];
        float2 b1 = cmul(x[b + 272], tw[TW_OFF4 + 3 * j + 0]);
        float2 b2 = cmul(x[b + 544], tw[TW_OFF4 + 3 * j + 1]);
        float2 b3 = cmul(x[b + 816], tw[TW_OFF4 + 3 * j + 2]);
        float2 t0 = make_float2(b0.x + b2.x, b0.y + b2.y);
        float2 t1 = make_float2(b0.x - b2.x, b0.y - b2.y);
        float2 t2 = make_float2(b1.x + b3.x, b1.y + b3.y);
        float2 t3 = make_float2(-(b1.y - b3.y), b1.x - b3.x);
        x[b]       = make_float2(t0.x + t2.x, t0.y + t2.y);  // y0 (rows 0-255)
        x[b + 816] = make_float2(t1.x - t3.x, t1.y - t3.y);  // y3 (rows 768+)
    }
}

// 8 independent 1024-pt inverse FFTs; 512 threads; padded rows pitch PITCH.
__device__ __forceinline__ void fft8x1024(float2* data, const float2* tw, int tid)
{
    stage16_01(data, tw, tid);
    __syncthreads();
    stage16_23(data, tw, tid);
    __syncthreads();
    stage4_last_pruned(data + (tid >> 6) * PITCH, tw, tid & 63);
    __syncthreads();
}

// ---------------------------------------------------------------------------
// FFT along kx on Hermitian-packed batch pairs. Block = column PAIR
// (iy, 1024-iy): 8 FFTs (4 packed x 2 columns), each grid cell read once.
// 513 blocks. Writes packed/compacted rows to g_fx (race-free).
// ---------------------------------------------------------------------------
__global__ __launch_bounds__(512)
void fft_x_kernel()
{
    extern __shared__ float2 sm[];
    float2* tw   = sm;
    float2* data = sm + TW_TOT;
    const int tid = threadIdx.x;
    init_tw(tw, tid, 512);

    const int iy  = blockIdx.x;                       // 0..512
    const int iyr = (KGRID - iy) & (KGRID - 1);

    for (int t = tid; t < 8 * KGRID; t += 512) {
        int ix = t >> 3;
        int r  = t & 7;                               // r = half*4 + p
        int p  = r & 3;
        int colX = (r < 4) ? iy  : iyr;               // this FFT's column
        int colM = (r < 4) ? iyr : iy;                // mirror column
        int ixr  = (KGRID - ix) & (KGRID - 1);
        const float4 A = *reinterpret_cast<const float4*>(
            &g_grid[(ix  * KGRID + colX) * BATCH + 2 * p]);
        const float4 B = *reinterpret_cast<const float4*>(
            &g_grid[(ixr * KGRID + colM) * BATCH + 2 * p]);
        float2 c;
        c.x = 0.5f * ((A.x + B.x) - (A.w - B.w));
        c.y = 0.5f * ((A.y - B.y) + (A.z + B.z));
        data[r * PITCH + pos17(digit_rev10(ix))] = c;
    }
    __syncthreads();

    fft8x1024(data, tw, tid);

    for (int t = tid; t < 8 * 512; t += 512) {
        int r  = t & 7;
        int xl = t >> 3;                       // compacted row 0..511
        int p  = r & 3;
        int colX = (r < 4) ? iy : iyr;
        int xg = (xl < 256) ? xl : xl + 512;   // source row in smem
        g_fx[(xl * KGRID + colX) * 4 + p] = data[r * PITCH + pos17(xg)];
    }
}

// ---------------------------------------------------------------------------
__device__ __forceinline__ float inv_apod(int i)
{
    float xv = ((float)i - 256.0f) * (1.0f / 1024.0f);
    float pj = PI_F * 6.0f * xv;
    float tv = BETA_F * BETA_F - pj * pj;
    float st = sqrtf(fabsf(tv));
    float num = (tv > 0.0f) ? sinhf(st) : sinf(st);
    return fmaxf(st, 1e-6f) / num;
}

// FFT along ky on packed data: 2 output rows x 4 packed FFTs; 256 blocks.
// Reads g_fx compacted rows; epilogue batch 2p = Re, 2p+1 = Im.
__global__ __launch_bounds__(512)
void fft_y_kernel(float* __restrict__ out)
{
    extern __shared__ float2 sm[];
    float2* tw   = sm;
    float2* data = sm + TW_TOT;
    const int tid = threadIdx.x;
    init_tw(tw, tid, 512);

    const int x_img0 = blockIdx.x * 2;
    int xsl[2];
    #pragma unroll
    for (int e = 0; e < 2; e++) {
        int x_src = ((x_img0 + e) + 768) & (KGRID - 1);
        xsl[e] = (x_src < 256) ? x_src : x_src - 512;   // compacted row
    }

    for (int t = tid; t < 8 * KGRID; t += 512) {
        int ky = t >> 3;
        int r  = t & 7;                        // r = e*4 + p
        int p  = r & 3;
        int e  = r >> 2;
        data[r * PITCH + pos17(digit_rev10(ky))] =
            g_fx[(xsl[e] * KGRID + ky) * 4 + p];
    }
    __syncthreads();

    fft8x1024(data, tw, tid);

    const float iax0 = inv_apod(x_img0);
    const float iax1 = inv_apod(x_img0 + 1);
    for (int t = tid; t < 8 * NIMG; t += 512) {
        int r  = t >> 9;                       // 0..7 = e*4 + p
        int yi = t & 511;
        int e  = r >> 2;
        int p  = r & 3;
        int ys = (yi + 768) & (KGRID - 1);     // in [0,256) U [768,1024)
        float2 v = data[r * PITCH + pos17(ys)];
        float scale = (e ? iax1 : iax0) * inv_apod(yi);
        int xi = x_img0 + e;
        out[(2 * p)     * (NIMG * NIMG) + xi * NIMG + yi] = v.x * scale;
        out[(2 * p + 1) * (NIMG * NIMG) + xi * NIMG + yi] = v.y * scale;
    }
}

// ---------------------------------------------------------------------------
extern "C" void kernel_launch(void* const* d_in, const int* in_sizes, int n_in,
                              void* d_out, int out_size)
{
    const float* yr  = (const float*)d_in[0];
    const float* yi  = (const float*)d_in[1];
    const float* uv  = (const float*)d_in[2];
    const float* wts = (const float*)d_in[3];
    float* out = (float*)d_out;

    const int smem_fft = (TW_TOT + 8 * PITCH) * (int)sizeof(float2); // ~77.9 KB
    cudaFuncSetAttribute(fft_x_kernel,
                         cudaFuncAttributeMaxDynamicSharedMemorySize, smem_fft);
    cudaFuncSetAttribute(fft_y_kernel,
                         cudaFuncAttributeMaxDynamicSharedMemorySize, smem_fft);

    zero_kernel<<<4096, 256>>>();
    scatter_kernel<<<(8 * MPTS + 255) / 256, 256>>>(yr, yi, uv, wts);
    fft_x_kernel<<<KGRID / 2 + 1, 512, smem_fft>>>();
    fft_y_kernel<<<NIMG / 2, 512, smem_fft>>>(out);
}

// round 16
// speedup vs baseline: 1.0282x; 1.0282x over previous
#include <cuda_runtime.h>
#include <math.h>

// ---------------------------------------------------------------------------
// NUFFT adjoint (Kaiser-Bessel gridding) for GB300 — round 16
// = R14 exactly (best: 129.8us; fused radix-16 FFT stages, R9 scatter/zero,
//   g_fx intermediate, 256-thread/4-FFT blocks)
// + fft_y stage-4 fused with the epilogue: pruned stage-4 outputs are scaled
//   and written straight to gmem from registers (coalesced), removing one
//   smem round trip + one __syncthreads. (R15's 512-thread variant reverted:
//   it regressed fft_y 17.7->21.6.)
// ---------------------------------------------------------------------------

#define KGRID   1024
#define NIMG    512
#define MPTS    200000
#define BATCH   8
#define JW      6
#define BETA_F  14.04f
#define PI_F    3.14159265358979f

#define GRID_F2 (KGRID * KGRID * BATCH)   // 64 MB
#define FX_F2   (NIMG * KGRID * 4)        // 16 MB packed fft_x output
#define PITCH   1092                      // 17*64 data + 4 pad (PITCH%16==4)

#define TW_OFF1 0
#define TW_OFF2 12
#define TW_OFF3 60
#define TW_OFF4 252
#define TW_TOT  1020

__device__ float2 g_grid[GRID_F2];
__device__ float2 g_fx[FX_F2];            // [xl][ky][p], xl = compacted row

// padded position of logical element n within a row
__device__ __forceinline__ int pos17(int n) { return 17 * (n >> 4) + (n & 15); }

// ---------------------------------------------------------------------------
__device__ __forceinline__ float bessel_i0(float x)
{
    if (x < 3.75f) {
        float t = x * (1.0f / 3.75f);
        t *= t;
        return 1.0f + t * (3.5156229f + t * (3.0899424f + t * (1.2067492f +
                     t * (0.2659732f + t * (0.0360768f + t * 0.0045813f)))));
    } else {
        float t = 3.75f / x;
        float p = 0.39894228f + t * (0.01328592f + t * (0.00225319f +
                  t * (-0.00157565f + t * (0.00916281f + t * (-0.02057706f +
                  t * (0.02635537f + t * (-0.01647633f + t * 0.00392377f)))))));
        return __expf(x) * rsqrtf(x) * p;
    }
}

// ---------------------------------------------------------------------------
// Zero the grid (64 MB). Also the L2 warm for the scatter's atomics.
// ---------------------------------------------------------------------------
__global__ void zero_kernel()
{
    float4* p = reinterpret_cast<float4*>(g_grid);
    const int n = GRID_F2 / 2;
    for (int i = blockIdx.x * blockDim.x + threadIdx.x; i < n;
         i += gridDim.x * blockDim.x)
        p[i] = make_float4(0.f, 0.f, 0.f, 0.f);
}

// ---------------------------------------------------------------------------
// Gridding scatter (R9): 8 threads per measurement; q = batch pair (lanes
// 0-3 write 4 contiguous 16B quarters of each 64B cell), h = x-tap half.
// ---------------------------------------------------------------------------
__global__ __launch_bounds__(256)
void scatter_kernel(const float* __restrict__ yr, const float* __restrict__ yi,
                    const float* __restrict__ uv, const float* __restrict__ wts)
{
    const int gid = blockIdx.x * blockDim.x + threadIdx.x;
    const int m = gid >> 3;
    const int q = gid & 3;                 // batches 2q, 2q+1
    const int h = (gid >> 2) & 1;          // a in {3h, 3h+1, 3h+2}
    if (m >= MPTS) return;

    const float2 c2 = reinterpret_cast<const float2*>(uv)[m];
    const float wt = wts[m];
    const float inv_i0b = 1.0f / bessel_i0(BETA_F);

    int ixv[3], iyv[JW];
    float wx[3], wy[JW];

    {
        float k  = c2.x / (2.0f * PI_F) * (float)KGRID;
        float km = floorf(k - 3.0f);
        #pragma unroll
        for (int j = 0; j < 3; j++) {
            int jj = 3 * h + j;
            float pt = km + (float)(jj + 1);
            float d  = k - pt;
            float arg = fmaxf(1.0f - d * d * (1.0f / 9.0f), 0.0f);
            wx[j] = bessel_i0(BETA_F * sqrtf(arg)) * inv_i0b;
            ixv[j] = ((int)pt + KGRID) & (KGRID - 1);
        }
    }
    {
        float k  = c2.y / (2.0f * PI_F) * (float)KGRID;
        float km = floorf(k - 3.0f);
        #pragma unroll
        for (int j = 0; j < JW; j++) {
            float pt = km + (float)(j + 1);
            float d  = k - pt;
            float arg = fmaxf(1.0f - d * d * (1.0f / 9.0f), 0.0f);
            wy[j] = bessel_i0(BETA_F * sqrtf(arg)) * inv_i0b;
            iyv[j] = ((int)pt + KGRID) & (KGRID - 1);
        }
    }

    const int b0 = 2 * q;
    const float yr0 = yr[b0 * MPTS + m] * wt;
    const float yi0 = yi[b0 * MPTS + m] * wt;
    const float yr1 = yr[(b0 + 1) * MPTS + m] * wt;
    const float yi1 = yi[(b0 + 1) * MPTS + m] * wt;

    #pragma unroll
    for (int a = 0; a < 3; a++) {
        const int rowbase = ixv[a] * KGRID;
        const float wxa = wx[a];
        #pragma unroll
        for (int c = 0; c < JW; c++) {
            const float w2 = wxa * wy[c];
            float* fp = reinterpret_cast<float*>(&g_grid[(rowbase + iyv[c]) * BATCH])
                        + 4 * q;
            asm volatile(
                "red.global.add.v4.f32 [%0], {%1, %2, %3, %4};"
                :: "l"(fp),
                   "f"(w2 * yr0), "f"(w2 * yi0),
                   "f"(w2 * yr1), "f"(w2 * yi1)
                : "memory");
        }
    }
}

// ---------------------------------------------------------------------------
// Radix-4/16 FFT machinery (inverse, e^{+i})
// ---------------------------------------------------------------------------
__device__ __forceinline__ int digit_rev10(int i)
{
    int r = (int)(__brev((unsigned)i) >> 22);
    return ((r & 0x155) << 1) | ((r & 0x2AA) >> 1);
}

__device__ __forceinline__ float2 cmul(float2 a, float2 b)
{
    return make_float2(a.x * b.x - a.y * b.y, a.x * b.y + a.y * b.x);
}

__device__ __forceinline__ void init_tw(float2* tw, int tid, int nthr)
{
    for (int t = tid; t < 340; t += nthr) {
        int s, j, off;
        if      (t < 4)  { s = 1; j = t;      off = TW_OFF1; }
        else if (t < 20) { s = 2; j = t - 4;  off = TW_OFF2; }
        else if (t < 84) { s = 3; j = t - 20; off = TW_OFF3; }
        else             { s = 4; j = t - 84; off = TW_OFF4; }
        int em = j << (8 - 2 * s);
        float a = (float)em * (2.0f * PI_F / 1024.0f);
        float s1, c1, s2, c2, s3, c3;
        __sincosf(a, &s1, &c1);
        __sincosf(2.0f * a, &s2, &c2);
        __sincosf(3.0f * a, &s3, &c3);
        tw[off + 3 * j + 0] = make_float2(c1, s1);
        tw[off + 3 * j + 1] = make_float2(c2, s2);
        tw[off + 3 * j + 2] = make_float2(c3, s3);
    }
}

__device__ __forceinline__ void rad4ip(float2& b0, float2& b1, float2& b2, float2& b3)
{
    float2 t0 = make_float2(b0.x + b2.x, b0.y + b2.y);
    float2 t1 = make_float2(b0.x - b2.x, b0.y - b2.y);
    float2 t2 = make_float2(b1.x + b3.x, b1.y + b3.y);
    float2 t3 = make_float2(-(b1.y - b3.y), b1.x - b3.x);   // +i*(b1-b3)
    b0 = make_float2(t0.x + t2.x, t0.y + t2.y);
    b1 = make_float2(t1.x + t3.x, t1.y + t3.y);
    b2 = make_float2(t0.x - t2.x, t0.y - t2.y);
    b3 = make_float2(t1.x - t3.x, t1.y - t3.y);
}

// stages 0+1 as a register radix-16 on 16 contiguous elements.
// 256 threads: fft row = tid&3, group g = tid>>2 (0..63).
__device__ __forceinline__ void stage16_01(float2* data, const float2* tw, int tid)
{
    float2* row = data + (tid & 3) * PITCH;
    const int base = 17 * (tid >> 2);
    float2 v[16];
    #pragma unroll
    for (int k = 0; k < 16; k++) v[k] = row[base + k];

    #pragma unroll
    for (int t = 0; t < 4; t++)                    // stage 0 (twiddle-free)
        rad4ip(v[4 * t], v[4 * t + 1], v[4 * t + 2], v[4 * t + 3]);

    #pragma unroll
    for (int t = 0; t < 4; t++) {                  // stage 1, j = t
        if (t > 0) {
            v[t + 4]  = cmul(v[t + 4],  tw[TW_OFF1 + 3 * t + 0]);
            v[t + 8]  = cmul(v[t + 8],  tw[TW_OFF1 + 3 * t + 1]);
            v[t + 12] = cmul(v[t + 12], tw[TW_OFF1 + 3 * t + 2]);
        }
        rad4ip(v[t], v[t + 4], v[t + 8], v[t + 12]);
    }
    #pragma unroll
    for (int k = 0; k < 16; k++) row[base + k] = v[k];
}

// stages 2+3 as a register radix-16 on stride-16 elements.
// 256 threads: fft row = tid&3, j0 = (tid>>2)&15, c = tid>>6.
__device__ __forceinline__ void stage16_23(float2* data, const float2* tw, int tid)
{
    float2* row = data + (tid & 3) * PITCH;
    const int j0 = (tid >> 2) & 15;
    const int c  = tid >> 6;
    const int base = 272 * c + j0;
    float2 v[16];
    #pragma unroll
    for (int k = 0; k < 16; k++) v[k] = row[base + 17 * k];

    {   // stage 2: twiddle j = j0
        const float2 w1 = tw[TW_OFF2 + 3 * j0 + 0];
        const float2 w2 = tw[TW_OFF2 + 3 * j0 + 1];
        const float2 w3 = tw[TW_OFF2 + 3 * j0 + 2];
        #pragma unroll
        for (int t = 0; t < 4; t++) {
            v[4 * t + 1] = cmul(v[4 * t + 1], w1);
            v[4 * t + 2] = cmul(v[4 * t + 2], w2);
            v[4 * t + 3] = cmul(v[4 * t + 3], w3);
            rad4ip(v[4 * t], v[4 * t + 1], v[4 * t + 2], v[4 * t + 3]);
        }
    }
    #pragma unroll
    for (int t = 0; t < 4; t++) {                  // stage 3: j = 16t + j0
        const int jj = 16 * t + j0;
        v[t + 4]  = cmul(v[t + 4],  tw[TW_OFF3 + 3 * jj + 0]);
        v[t + 8]  = cmul(v[t + 8],  tw[TW_OFF3 + 3 * jj + 1]);
        v[t + 12] = cmul(v[t + 12], tw[TW_OFF3 + 3 * jj + 2]);
        rad4ip(v[t], v[t + 4], v[t + 8], v[t + 12]);
    }
    #pragma unroll
    for (int k = 0; k < 16; k++) row[base + 17 * k] = v[k];
}

// Final stage (S=4), pruned to fftshift+crop survivors; results to smem
// (used by fft_x, whose output loop needs p-merged global stores).
__device__ __forceinline__ void stage4_last_pruned(float2* x, const float2* tw,
                                                   int bi0)
{
    #pragma unroll
    for (int u = 0; u < 4; u++) {
        const int j = bi0 + (u << 6);
        const int b = 17 * (j >> 4) + (j & 15);
        float2 b0 = x[b];
        float2 b1 = cmul(x[b + 272], tw[TW_OFF4 + 3 * j + 0]);
        float2 b2 = cmul(x[b + 544], tw[TW_OFF4 + 3 * j + 1]);
        float2 b3 = cmul(x[b + 816], tw[TW_OFF4 + 3 * j + 2]);
        float2 t0 = make_float2(b0.x + b2.x, b0.y + b2.y);
        float2 t1 = make_float2(b0.x - b2.x, b0.y - b2.y);
        float2 t2 = make_float2(b1.x + b3.x, b1.y + b3.y);
        float2 t3 = make_float2(-(b1.y - b3.y), b1.x - b3.x);
        x[b]       = make_float2(t0.x + t2.x, t0.y + t2.y);  // y0 (rows 0-255)
        x[b + 816] = make_float2(t1.x - t3.x, t1.y - t3.y);  // y3 (rows 768+)
    }
}

// ---------------------------------------------------------------------------
__device__ __forceinline__ float inv_apod(int i)
{
    float xv = ((float)i - 256.0f) * (1.0f / 1024.0f);
    float pj = PI_F * 6.0f * xv;
    float tv = BETA_F * BETA_F - pj * pj;
    float st = sqrtf(fabsf(tv));
    float num = (tv > 0.0f) ? sinhf(st) : sinf(st);
    return fmaxf(st, 1e-6f) / num;
}

// ---------------------------------------------------------------------------
// FFT along kx on Hermitian-packed batch pairs. Block b: iy = b>>1,
// half = b&1 -> output column colA; 4 packed FFTs; 1026 blocks.
// Reads g_grid (read-only here); writes packed/compacted rows to g_fx.
// ---------------------------------------------------------------------------
__global__ __launch_bounds__(256)
void fft_x_kernel()
{
    extern __shared__ float2 sm[];
    float2* tw   = sm;
    float2* data = sm + TW_TOT;
    const int tid = threadIdx.x;
    init_tw(tw, tid, 256);

    const int iy   = blockIdx.x >> 1;                 // 0..512
    const int half = blockIdx.x & 1;
    const int iyr  = (KGRID - iy) & (KGRID - 1);
    const int colA = half ? iyr : iy;                 // output column
    const int colB = half ? iy  : iyr;                // mirror column

    for (int t = tid; t < 4 * KGRID; t += 256) {
        int ix  = t >> 2;
        int p   = t & 3;
        int ixr = (KGRID - ix) & (KGRID - 1);
        const float4 A = *reinterpret_cast<const float4*>(
            &g_grid[(ix  * KGRID + colA) * BATCH + 2 * p]);
        const float4 B = *reinterpret_cast<const float4*>(
            &g_grid[(ixr * KGRID + colB) * BATCH + 2 * p]);
        float2 c;
        c.x = 0.5f * ((A.x + B.x) - (A.w - B.w));
        c.y = 0.5f * ((A.y - B.y) + (A.z + B.z));
        data[p * PITCH + pos17(digit_rev10(ix))] = c;
    }
    __syncthreads();

    stage16_01(data, tw, tid);
    __syncthreads();
    stage16_23(data, tw, tid);
    __syncthreads();
    stage4_last_pruned(data + (tid >> 6) * PITCH, tw, tid & 63);
    __syncthreads();

    for (int t = tid; t < 4 * 512; t += 256) {
        int xl = t >> 2;                       // compacted row 0..511
        int p  = t & 3;
        int xg = (xl < 256) ? xl : xl + 512;   // source row in smem
        g_fx[(xl * KGRID + colA) * 4 + p] = data[p * PITCH + pos17(xg)];
    }
}

// ---------------------------------------------------------------------------
// FFT along ky on packed data: 1 x row x 4 packed FFTs; 512 blocks.
// Stage 4 fused with the epilogue: pruned outputs scaled + stored straight
// to gmem from registers (consecutive lanes -> consecutive yi -> coalesced).
//   n = j     -> yi = j + 256 ; n = j + 768 -> yi = j.
// ---------------------------------------------------------------------------
__global__ __launch_bounds__(256)
void fft_y_kernel(float* __restrict__ out)
{
    extern __shared__ float2 sm[];
    float2* tw   = sm;
    float2* data = sm + TW_TOT;
    const int tid = threadIdx.x;
    init_tw(tw, tid, 256);

    const int x_img = blockIdx.x;
    const int x_src = (x_img + 768) & (KGRID - 1);
    const int xl    = (x_src < 256) ? x_src : x_src - 512;   // compacted row
    const float2* grow = &g_fx[xl * (KGRID * 4)];

    for (int t = tid; t < 4 * KGRID; t += 256) {
        int ky = t >> 2;
        int p  = t & 3;
        data[p * PITCH + pos17(digit_rev10(ky))] = grow[t];
    }
    __syncthreads();

    stage16_01(data, tw, tid);
    __syncthreads();
    stage16_23(data, tw, tid);
    __syncthreads();

    // fused stage 4 + epilogue
    {
        const int p   = tid >> 6;              // 0..3
        const int bi0 = tid & 63;
        float2* x = data + p * PITCH;
        const float iax = inv_apod(x_img);
        float* outr = out + (2 * p)     * (NIMG * NIMG) + x_img * NIMG;
        float* outi = out + (2 * p + 1) * (NIMG * NIMG) + x_img * NIMG;

        #pragma unroll
        for (int u = 0; u < 4; u++) {
            const int j = bi0 + (u << 6);
            const int b = 17 * (j >> 4) + (j & 15);
            float2 b0 = x[b];
            float2 b1 = cmul(x[b + 272], tw[TW_OFF4 + 3 * j + 0]);
            float2 b2 = cmul(x[b + 544], tw[TW_OFF4 + 3 * j + 1]);
            float2 b3 = cmul(x[b + 816], tw[TW_OFF4 + 3 * j + 2]);
            float2 t0 = make_float2(b0.x + b2.x, b0.y + b2.y);
            float2 t1 = make_float2(b0.x - b2.x, b0.y - b2.y);
            float2 t2 = make_float2(b1.x + b3.x, b1.y + b3.y);
            float2 t3 = make_float2(-(b1.y - b3.y), b1.x - b3.x);
            float2 y0 = make_float2(t0.x + t2.x, t0.y + t2.y);   // n = j
            float2 y3 = make_float2(t1.x - t3.x, t1.y - t3.y);   // n = j+768

            const float s0 = iax * inv_apod(j + 256);  // yi = j+256
            const float s3 = iax * inv_apod(j);        // yi = j
            outr[j + 256] = y0.x * s0;
            outi[j + 256] = y0.y * s0;
            outr[j]       = y3.x * s3;
            outi[j]       = y3.y * s3;
        }
    }
}

// ---------------------------------------------------------------------------
extern "C" void kernel_launch(void* const* d_in, const int* in_sizes, int n_in,
                              void* d_out, int out_size)
{
    const float* yr  = (const float*)d_in[0];
    const float* yi  = (const float*)d_in[1];
    const float* uv  = (const float*)d_in[2];
    const float* wts = (const float*)d_in[3];
    float* out = (float*)d_out;

    const int smem_fft = (TW_TOT + 4 * PITCH) * (int)sizeof(float2); // ~43.1 KB
    cudaFuncSetAttribute(fft_x_kernel,
                         cudaFuncAttributeMaxDynamicSharedMemorySize, smem_fft);
    cudaFuncSetAttribute(fft_y_kernel,
                         cudaFuncAttributeMaxDynamicSharedMemorySize, smem_fft);

    zero_kernel<<<4096, 256>>>();
    scatter_kernel<<<(8 * MPTS + 255) / 256, 256>>>(yr, yi, uv, wts);
    fft_x_kernel<<<2 * (KGRID / 2 + 1), 256, smem_fft>>>();
    fft_y_kernel<<<NIMG, 256, smem_fft>>>(out);
}

// round 17
// speedup vs baseline: 1.0444x; 1.0158x over previous
#include <cuda_runtime.h>
#include <math.h>

// ---------------------------------------------------------------------------
// NUFFT adjoint (Kaiser-Bessel gridding) for GB300 — round 17
// = R16 (129.5us: fused radix-16 FFT, fused fft_y epilogue, R9 scatter)
// + zero_kernel ELIMINATED: fft_y (the last kernel) blind-zeroes all of
//   g_grid (128KB/block, no race — fft_y never reads g_grid). Dirty-zero
//   lines stay L2-resident for the next replay's scatter (stronger than the
//   old zero_kernel warm since nothing runs in between).
// + fft_y apodization from a 512-entry smem table (removes 8 sinh/sin
//   chains per thread from the fused epilogue).
// ---------------------------------------------------------------------------

#define KGRID   1024
#define NIMG    512
#define MPTS    200000
#define BATCH   8
#define JW      6
#define BETA_F  14.04f
#define PI_F    3.14159265358979f

#define GRID_F2 (KGRID * KGRID * BATCH)   // 64 MB
#define FX_F2   (NIMG * KGRID * 4)        // 16 MB packed fft_x output
#define PITCH   1092                      // 17*64 data + 4 pad (PITCH%16==4)

#define TW_OFF1 0
#define TW_OFF2 12
#define TW_OFF3 60
#define TW_OFF4 252
#define TW_TOT  1020

__device__ float2 g_grid[GRID_F2];        // zero-initialized at module load;
                                          // left all-zero by every launch
__device__ float2 g_fx[FX_F2];            // [xl][ky][p], xl = compacted row

// padded position of logical element n within a row
__device__ __forceinline__ int pos17(int n) { return 17 * (n >> 4) + (n & 15); }

// ---------------------------------------------------------------------------
__device__ __forceinline__ float bessel_i0(float x)
{
    if (x < 3.75f) {
        float t = x * (1.0f / 3.75f);
        t *= t;
        return 1.0f + t * (3.5156229f + t * (3.0899424f + t * (1.2067492f +
                     t * (0.2659732f + t * (0.0360768f + t * 0.0045813f)))));
    } else {
        float t = 3.75f / x;
        float p = 0.39894228f + t * (0.00225319f * 0.0f + 0.01328592f + t * (0.00225319f +
                  t * (-0.00157565f + t * (0.00916281f + t * (-0.02057706f +
                  t * (0.02635537f + t * (-0.01647633f + t * 0.00392377f)))))));
        return __expf(x) * rsqrtf(x) * p;
    }
}

// ---------------------------------------------------------------------------
// Gridding scatter (R9): 8 threads per measurement; q = batch pair (lanes
// 0-3 write 4 contiguous 16B quarters of each 64B cell), h = x-tap half.
// ---------------------------------------------------------------------------
__global__ __launch_bounds__(256)
void scatter_kernel(const float* __restrict__ yr, const float* __restrict__ yi,
                    const float* __restrict__ uv, const float* __restrict__ wts)
{
    const int gid = blockIdx.x * blockDim.x + threadIdx.x;
    const int m = gid >> 3;
    const int q = gid & 3;                 // batches 2q, 2q+1
    const int h = (gid >> 2) & 1;          // a in {3h, 3h+1, 3h+2}
    if (m >= MPTS) return;

    const float2 c2 = reinterpret_cast<const float2*>(uv)[m];
    const float wt = wts[m];
    const float inv_i0b = 1.0f / bessel_i0(BETA_F);

    int ixv[3], iyv[JW];
    float wx[3], wy[JW];

    {
        float k  = c2.x / (2.0f * PI_F) * (float)KGRID;
        float km = floorf(k - 3.0f);
        #pragma unroll
        for (int j = 0; j < 3; j++) {
            int jj = 3 * h + j;
            float pt = km + (float)(jj + 1);
            float d  = k - pt;
            float arg = fmaxf(1.0f - d * d * (1.0f / 9.0f), 0.0f);
            wx[j] = bessel_i0(BETA_F * sqrtf(arg)) * inv_i0b;
            ixv[j] = ((int)pt + KGRID) & (KGRID - 1);
        }
    }
    {
        float k  = c2.y / (2.0f * PI_F) * (float)KGRID;
        float km = floorf(k - 3.0f);
        #pragma unroll
        for (int j = 0; j < JW; j++) {
            float pt = km + (float)(j + 1);
            float d  = k - pt;
            float arg = fmaxf(1.0f - d * d * (1.0f / 9.0f), 0.0f);
            wy[j] = bessel_i0(BETA_F * sqrtf(arg)) * inv_i0b;
            iyv[j] = ((int)pt + KGRID) & (KGRID - 1);
        }
    }

    const int b0 = 2 * q;
    const float yr0 = yr[b0 * MPTS + m] * wt;
    const float yi0 = yi[b0 * MPTS + m] * wt;
    const float yr1 = yr[(b0 + 1) * MPTS + m] * wt;
    const float yi1 = yi[(b0 + 1) * MPTS + m] * wt;

    #pragma unroll
    for (int a = 0; a < 3; a++) {
        const int rowbase = ixv[a] * KGRID;
        const float wxa = wx[a];
        #pragma unroll
        for (int c = 0; c < JW; c++) {
            const float w2 = wxa * wy[c];
            float* fp = reinterpret_cast<float*>(&g_grid[(rowbase + iyv[c]) * BATCH])
                        + 4 * q;
            asm volatile(
                "red.global.add.v4.f32 [%0], {%1, %2, %3, %4};"
                :: "l"(fp),
                   "f"(w2 * yr0), "f"(w2 * yi0),
                   "f"(w2 * yr1), "f"(w2 * yi1)
                : "memory");
        }
    }
}

// ---------------------------------------------------------------------------
// Radix-4/16 FFT machinery (inverse, e^{+i})
// ---------------------------------------------------------------------------
__device__ __forceinline__ int digit_rev10(int i)
{
    int r = (int)(__brev((unsigned)i) >> 22);
    return ((r & 0x155) << 1) | ((r & 0x2AA) >> 1);
}

__device__ __forceinline__ float2 cmul(float2 a, float2 b)
{
    return make_float2(a.x * b.x - a.y * b.y, a.x * b.y + a.y * b.x);
}

__device__ __forceinline__ void init_tw(float2* tw, int tid, int nthr)
{
    for (int t = tid; t < 340; t += nthr) {
        int s, j, off;
        if      (t < 4)  { s = 1; j = t;      off = TW_OFF1; }
        else if (t < 20) { s = 2; j = t - 4;  off = TW_OFF2; }
        else if (t < 84) { s = 3; j = t - 20; off = TW_OFF3; }
        else             { s = 4; j = t - 84; off = TW_OFF4; }
        int em = j << (8 - 2 * s);
        float a = (float)em * (2.0f * PI_F / 1024.0f);
        float s1, c1, s2, c2, s3, c3;
        __sincosf(a, &s1, &c1);
        __sincosf(2.0f * a, &s2, &c2);
        __sincosf(3.0f * a, &s3, &c3);
        tw[off + 3 * j + 0] = make_float2(c1, s1);
        tw[off + 3 * j + 1] = make_float2(c2, s2);
        tw[off + 3 * j + 2] = make_float2(c3, s3);
    }
}

__device__ __forceinline__ void rad4ip(float2& b0, float2& b1, float2& b2, float2& b3)
{
    float2 t0 = make_float2(b0.x + b2.x, b0.y + b2.y);
    float2 t1 = make_float2(b0.x - b2.x, b0.y - b2.y);
    float2 t2 = make_float2(b1.x + b3.x, b1.y + b3.y);
    float2 t3 = make_float2(-(b1.y - b3.y), b1.x - b3.x);   // +i*(b1-b3)
    b0 = make_float2(t0.x + t2.x, t0.y + t2.y);
    b1 = make_float2(t1.x + t3.x, t1.y + t3.y);
    b2 = make_float2(t0.x - t2.x, t0.y - t2.y);
    b3 = make_float2(t1.x - t3.x, t1.y - t3.y);
}

// stages 0+1 as a register radix-16 on 16 contiguous elements.
// 256 threads: fft row = tid&3, group g = tid>>2 (0..63).
__device__ __forceinline__ void stage16_01(float2* data, const float2* tw, int tid)
{
    float2* row = data + (tid & 3) * PITCH;
    const int base = 17 * (tid >> 2);
    float2 v[16];
    #pragma unroll
    for (int k = 0; k < 16; k++) v[k] = row[base + k];

    #pragma unroll
    for (int t = 0; t < 4; t++)                    // stage 0 (twiddle-free)
        rad4ip(v[4 * t], v[4 * t + 1], v[4 * t + 2], v[4 * t + 3]);

    #pragma unroll
    for (int t = 0; t < 4; t++) {                  // stage 1, j = t
        if (t > 0) {
            v[t + 4]  = cmul(v[t + 4],  tw[TW_OFF1 + 3 * t + 0]);
            v[t + 8]  = cmul(v[t + 8],  tw[TW_OFF1 + 3 * t + 1]);
            v[t + 12] = cmul(v[t + 12], tw[TW_OFF1 + 3 * t + 2]);
        }
        rad4ip(v[t], v[t + 4], v[t + 8], v[t + 12]);
    }
    #pragma unroll
    for (int k = 0; k < 16; k++) row[base + k] = v[k];
}

// stages 2+3 as a register radix-16 on stride-16 elements.
// 256 threads: fft row = tid&3, j0 = (tid>>2)&15, c = tid>>6.
__device__ __forceinline__ void stage16_23(float2* data, const float2* tw, int tid)
{
    float2* row = data + (tid & 3) * PITCH;
    const int j0 = (tid >> 2) & 15;
    const int c  = tid >> 6;
    const int base = 272 * c + j0;
    float2 v[16];
    #pragma unroll
    for (int k = 0; k < 16; k++) v[k] = row[base + 17 * k];

    {   // stage 2: twiddle j = j0
        const float2 w1 = tw[TW_OFF2 + 3 * j0 + 0];
        const float2 w2 = tw[TW_OFF2 + 3 * j0 + 1];
        const float2 w3 = tw[TW_OFF2 + 3 * j0 + 2];
        #pragma unroll
        for (int t = 0; t < 4; t++) {
            v[4 * t + 1] = cmul(v[4 * t + 1], w1);
            v[4 * t + 2] = cmul(v[4 * t + 2], w2);
            v[4 * t + 3] = cmul(v[4 * t + 3], w3);
            rad4ip(v[4 * t], v[4 * t + 1], v[4 * t + 2], v[4 * t + 3]);
        }
    }
    #pragma unroll
    for (int t = 0; t < 4; t++) {                  // stage 3: j = 16t + j0
        const int jj = 16 * t + j0;
        v[t + 4]  = cmul(v[t + 4],  tw[TW_OFF3 + 3 * jj + 0]);
        v[t + 8]  = cmul(v[t + 8],  tw[TW_OFF3 + 3 * jj + 1]);
        v[t + 12] = cmul(v[t + 12], tw[TW_OFF3 + 3 * jj + 2]);
        rad4ip(v[t], v[t + 4], v[t + 8], v[t + 12]);
    }
    #pragma unroll
    for (int k = 0; k < 16; k++) row[base + 17 * k] = v[k];
}

// Final stage (S=4), pruned to fftshift+crop survivors; results to smem
// (used by fft_x, whose output loop needs p-merged global stores).
__device__ __forceinline__ void stage4_last_pruned(float2* x, const float2* tw,
                                                   int bi0)
{
    #pragma unroll
    for (int u = 0; u < 4; u++) {
        const int j = bi0 + (u << 6);
        const int b = 17 * (j >> 4) + (j & 15);
        float2 b0 = x[b];
        float2 b1 = cmul(x[b + 272], tw[TW_OFF4 + 3 * j + 0]);
        float2 b2 = cmul(x[b + 544], tw[TW_OFF4 + 3 * j + 1]);
        float2 b3 = cmul(x[b + 816], tw[TW_OFF4 + 3 * j + 2]);
        float2 t0 = make_float2(b0.x + b2.x, b0.y + b2.y);
        float2 t1 = make_float2(b0.x - b2.x, b0.y - b2.y);
        float2 t2 = make_float2(b1.x + b3.x, b1.y + b3.y);
        float2 t3 = make_float2(-(b1.y - b3.y), b1.x - b3.x);
        x[b]       = make_float2(t0.x + t2.x, t0.y + t2.y);  // y0 (rows 0-255)
        x[b + 816] = make_float2(t1.x - t3.x, t1.y - t3.y);  // y3 (rows 768+)
    }
}

// ---------------------------------------------------------------------------
__device__ __forceinline__ float inv_apod(int i)
{
    float xv = ((float)i - 256.0f) * (1.0f / 1024.0f);
    float pj = PI_F * 6.0f * xv;
    float tv = BETA_F * BETA_F - pj * pj;
    float st = sqrtf(fabsf(tv));
    float num = (tv > 0.0f) ? sinhf(st) : sinf(st);
    return fmaxf(st, 1e-6f) / num;
}

// ---------------------------------------------------------------------------
// FFT along kx on Hermitian-packed batch pairs. Block b: iy = b>>1,
// half = b&1 -> output column colA; 4 packed FFTs; 1026 blocks.
// Reads g_grid (read-only here); writes packed/compacted rows to g_fx.
// ---------------------------------------------------------------------------
__global__ __launch_bounds__(256)
void fft_x_kernel()
{
    extern __shared__ float2 sm[];
    float2* tw   = sm;
    float2* data = sm + TW_TOT;
    const int tid = threadIdx.x;
    init_tw(tw, tid, 256);

    const int iy   = blockIdx.x >> 1;                 // 0..512
    const int half = blockIdx.x & 1;
    const int iyr  = (KGRID - iy) & (KGRID - 1);
    const int colA = half ? iyr : iy;                 // output column
    const int colB = half ? iy  : iyr;                // mirror column

    for (int t = tid; t < 4 * KGRID; t += 256) {
        int ix  = t >> 2;
        int p   = t & 3;
        int ixr = (KGRID - ix) & (KGRID - 1);
        const float4 A = *reinterpret_cast<const float4*>(
            &g_grid[(ix  * KGRID + colA) * BATCH + 2 * p]);
        const float4 B = *reinterpret_cast<const float4*>(
            &g_grid[(ixr * KGRID + colB) * BATCH + 2 * p]);
        float2 c;
        c.x = 0.5f * ((A.x + B.x) - (A.w - B.w));
        c.y = 0.5f * ((A.y - B.y) + (A.z + B.z));
        data[p * PITCH + pos17(digit_rev10(ix))] = c;
    }
    __syncthreads();

    stage16_01(data, tw, tid);
    __syncthreads();
    stage16_23(data, tw, tid);
    __syncthreads();
    stage4_last_pruned(data + (tid >> 6) * PITCH, tw, tid & 63);
    __syncthreads();

    for (int t = tid; t < 4 * 512; t += 256) {
        int xl = t >> 2;                       // compacted row 0..511
        int p  = t & 3;
        int xg = (xl < 256) ? xl : xl + 512;   // source row in smem
        g_fx[(xl * KGRID + colA) * 4 + p] = data[p * PITCH + pos17(xg)];
    }
}

// ---------------------------------------------------------------------------
// FFT along ky on packed data: 1 x row x 4 packed FFTs; 512 blocks.
// Also blind-zeroes its 128KB slice of g_grid (for the next launch's
// scatter; dirty-zero lines stay L2-resident). Stage 4 fused with epilogue;
// apodization factors from a 512-entry smem table.
// ---------------------------------------------------------------------------
__global__ __launch_bounds__(256)
void fft_y_kernel(float* __restrict__ out)
{
    extern __shared__ float2 sm[];
    float2* tw   = sm;
    float2* data = sm + TW_TOT;
    float*  ap   = reinterpret_cast<float*>(sm + TW_TOT + 4 * PITCH);
    const int tid = threadIdx.x;
    init_tw(tw, tid, 256);
    for (int t = tid; t < 512; t += 256)
        ap[t] = inv_apod(t);

    const int x_img = blockIdx.x;
    const int x_src = (x_img + 768) & (KGRID - 1);
    const int xl    = (x_src < 256) ? x_src : x_src - 512;   // compacted row
    const float2* grow = &g_fx[xl * (KGRID * 4)];

    for (int t = tid; t < 4 * KGRID; t += 256) {
        int ky = t >> 2;
        int p  = t & 3;
        data[p * PITCH + pos17(digit_rev10(ky))] = grow[t];
    }

    // blind-zero this block's 128KB slice of g_grid (no dependency, no race)
    {
        float4* gz = reinterpret_cast<float4*>(g_grid) + blockIdx.x * 8192;
        const float4 z4 = make_float4(0.f, 0.f, 0.f, 0.f);
        #pragma unroll 4
        for (int i = tid; i < 8192; i += 256) gz[i] = z4;
    }
    __syncthreads();

    stage16_01(data, tw, tid);
    __syncthreads();
    stage16_23(data, tw, tid);
    __syncthreads();

    // fused stage 4 + epilogue (apod from smem table)
    {
        const int p   = tid >> 6;              // 0..3
        const int bi0 = tid & 63;
        float2* x = data + p * PITCH;
        const float iax = ap[x_img];
        float* outr = out + (2 * p)     * (NIMG * NIMG) + x_img * NIMG;
        float* outi = out + (2 * p + 1) * (NIMG * NIMG) + x_img * NIMG;

        #pragma unroll
        for (int u = 0; u < 4; u++) {
            const int j = bi0 + (u << 6);
            const int b = 17 * (j >> 4) + (j & 15);
            float2 b0 = x[b];
            float2 b1 = cmul(x[b + 272], tw[TW_OFF4 + 3 * j + 0]);
            float2 b2 = cmul(x[b + 544], tw[TW_OFF4 + 3 * j + 1]);
            float2 b3 = cmul(x[b + 816], tw[TW_OFF4 + 3 * j + 2]);
            float2 t0 = make_float2(b0.x + b2.x, b0.y + b2.y);
            float2 t1 = make_float2(b0.x - b2.x, b0.y - b2.y);
            float2 t2 = make_float2(b1.x + b3.x, b1.y + b3.y);
            float2 t3 = make_float2(-(b1.y - b3.y), b1.x - b3.x);
            float2 y0 = make_float2(t0.x + t2.x, t0.y + t2.y);   // n = j
            float2 y3 = make_float2(t1.x - t3.x, t1.y - t3.y);   // n = j+768

            const float s0 = iax * ap[j + 256];   // yi = j+256
            const float s3 = iax * ap[j];         // yi = j
            outr[j + 256] = y0.x * s0;
            outi[j + 256] = y0.y * s0;
            outr[j]       = y3.x * s3;
            outi[j]       = y3.y * s3;
        }
    }
}

// ---------------------------------------------------------------------------
extern "C" void kernel_launch(void* const* d_in, const int* in_sizes, int n_in,
                              void* d_out, int out_size)
{
    const float* yr  = (const float*)d_in[0];
    const float* yi  = (const float*)d_in[1];
    const float* uv  = (const float*)d_in[2];
    const float* wts = (const float*)d_in[3];
    float* out = (float*)d_out;

    const int smem_fx = (TW_TOT + 4 * PITCH) * (int)sizeof(float2);  // ~43.1 KB
    const int smem_fy = smem_fx + 512 * (int)sizeof(float);          // + 2 KB
    cudaFuncSetAttribute(fft_x_kernel,
                         cudaFuncAttributeMaxDynamicSharedMemorySize, smem_fx);
    cudaFuncSetAttribute(fft_y_kernel,
                         cudaFuncAttributeMaxDynamicSharedMemorySize, smem_fy);

    scatter_kernel<<<(8 * MPTS + 255) / 256, 256>>>(yr, yi, uv, wts);
    fft_x_kernel<<<2 * (KGRID / 2 + 1), 256, smem_fx>>>();
    fft_y_kernel<<<NIMG, 256, smem_fy>>>(out);
}